// round 6
// baseline (speedup 1.0000x reference)
#include <cuda_runtime.h>
#include <cuda_bf16.h>

// PointInstanceNorm — per-segment pipelined version.
// x: [N,D] fp32; seqlen: [B+1] cumulative; weight/bias: [D].
// out[i,d] = (x[i,d]-mean[b,d]) * rsqrt(var[b,d]+eps) * w[d] + bias[d].
//
// R4 lesson: L2 reuse (read x once from DRAM) works, but software grid
// barriers cost ~11-20us each in straggler skew. This version gets the same
// reuse with HW-scheduled kernels:
//   side stream:  reduce(0) -> reduce(1) -> ... (each segment: 32MB, stays in L2)
//   main stream:  norm(b) waits on reduce(b) via event, reads x_b from L2
//   backpressure: reduce(b+1) waits on norm(b-1)  (L2 set ~96MB < 126MB)
// norm(b) overlaps reduce(b+1), so DRAM stays saturated. Total DRAM ~1.0GB.

#define PIN_EPS 1e-5f
#define PIN_MAXBD (1 << 20)
#define PIN_MAXB  64

__device__ float g_sum[PIN_MAXBD];
__device__ float g_sq [PIN_MAXBD];
// fallback-path scratch
__device__ float g_scale[PIN_MAXBD];
__device__ float g_shift[PIN_MAXBD];

__global__ void pin_zero_kernel(int n) {
    int i = blockIdx.x * blockDim.x + threadIdx.x;
    if (i < n) { g_sum[i] = 0.0f; g_sq[i] = 0.0f; }
}

// ---------------------------------------------------------------------------
// Per-segment reduce: blockDim=256, contiguous row chunk per block.
// Plain loads so segment b stays resident in L2 for the following norm(b).
// ---------------------------------------------------------------------------
__global__ void __launch_bounds__(256)
pin_reduce_seg(const float* __restrict__ x,
               const int*   __restrict__ seqlen,
               int b, int D4) {
    const long long s = seqlen[b];
    const long long e = seqlen[b + 1];
    const int L  = (int)(e - s);
    const int nb = gridDim.x;
    const int chunk = (L + nb - 1) / nb;
    const long long r0 = s + (long long)blockIdx.x * chunk;
    const long long r1 = s + (long long)min((long long)L,
                                            (long long)(blockIdx.x + 1) * (long long)chunk);
    const int lane = threadIdx.x % D4;
    const int grp  = threadIdx.x / D4;
    const int ngrp = blockDim.x / D4;
    const int D    = D4 * 4;

    float4 sum = make_float4(0.f, 0.f, 0.f, 0.f);
    float4 sq  = make_float4(0.f, 0.f, 0.f, 0.f);

    if (grp < ngrp) {
        const float4* __restrict__ x4 = (const float4*)x;
        for (long long r = r0 + grp; r < r1; r += ngrp) {
            float4 v = x4[r * D4 + lane];         // default policy: keep in L2
            sum.x += v.x; sum.y += v.y; sum.z += v.z; sum.w += v.w;
            sq.x  += v.x * v.x; sq.y += v.y * v.y;
            sq.z  += v.z * v.z; sq.w += v.w * v.w;
        }
    }

    __shared__ float4 s_sum[256];
    __shared__ float4 s_sq [256];
    s_sum[threadIdx.x] = sum;
    s_sq [threadIdx.x] = sq;
    __syncthreads();

    if (grp == 0) {
        for (int g = 1; g < ngrp; g++) {
            float4 a = s_sum[g * D4 + lane];
            float4 c = s_sq [g * D4 + lane];
            sum.x += a.x; sum.y += a.y; sum.z += a.z; sum.w += a.w;
            sq.x  += c.x; sq.y  += c.y; sq.z  += c.z; sq.w  += c.w;
        }
        const int base = b * D + lane * 4;
        atomicAdd(&g_sum[base + 0], sum.x);
        atomicAdd(&g_sum[base + 1], sum.y);
        atomicAdd(&g_sum[base + 2], sum.z);
        atomicAdd(&g_sum[base + 3], sum.w);
        atomicAdd(&g_sq [base + 0], sq.x);
        atomicAdd(&g_sq [base + 1], sq.y);
        atomicAdd(&g_sq [base + 2], sq.z);
        atomicAdd(&g_sq [base + 3], sq.w);
    }
}

// ---------------------------------------------------------------------------
// Per-segment normalize: finalize is folded in (each thread derives
// scale/shift for its 4 channels from the L2-hot accumulators).
// x reads use .cs (last use, evict-first); out writes use .cs (streaming).
// ---------------------------------------------------------------------------
__global__ void __launch_bounds__(256)
pin_norm_seg(const float* __restrict__ x,
             const int*   __restrict__ seqlen,
             const float* __restrict__ w,
             const float* __restrict__ bias,
             float*       __restrict__ out,
             int b, int D4) {
    const long long s = seqlen[b];
    const long long e = seqlen[b + 1];
    const int L  = (int)(e - s);
    const int nb = gridDim.x;
    const int chunk = (L + nb - 1) / nb;
    const long long r0 = s + (long long)blockIdx.x * chunk;
    const long long r1 = s + (long long)min((long long)L,
                                            (long long)(blockIdx.x + 1) * (long long)chunk);
    const int lane = threadIdx.x % D4;
    const int grp  = threadIdx.x / D4;
    const int ngrp = blockDim.x / D4;
    if (grp >= ngrp) return;

    // local finalize for this lane's 4 channels
    const float cnt   = (float)(e - s);
    const float inv_n = 1.0f / fmaxf(cnt, 1.0f);
    float4 sm = __ldcg(((const float4*)g_sum) + b * D4 + lane);
    float4 s2 = __ldcg(((const float4*)g_sq ) + b * D4 + lane);
    float4 wv = __ldg (((const float4*)w)    + lane);
    float4 bv = __ldg (((const float4*)bias) + lane);

    float4 mean, scale, shift;
    mean.x = sm.x * inv_n; mean.y = sm.y * inv_n;
    mean.z = sm.z * inv_n; mean.w = sm.w * inv_n;
    scale.x = rsqrtf(fmaxf(s2.x * inv_n - mean.x * mean.x, 0.f) + PIN_EPS) * wv.x;
    scale.y = rsqrtf(fmaxf(s2.y * inv_n - mean.y * mean.y, 0.f) + PIN_EPS) * wv.y;
    scale.z = rsqrtf(fmaxf(s2.z * inv_n - mean.z * mean.z, 0.f) + PIN_EPS) * wv.z;
    scale.w = rsqrtf(fmaxf(s2.w * inv_n - mean.w * mean.w, 0.f) + PIN_EPS) * wv.w;
    shift.x = bv.x - mean.x * scale.x;
    shift.y = bv.y - mean.y * scale.y;
    shift.z = bv.z - mean.z * scale.z;
    shift.w = bv.w - mean.w * scale.w;

    const float4* __restrict__ x4 = (const float4*)x;
    float4*       __restrict__ o4 = (float4*)out;
    for (long long r = r0 + grp; r < r1; r += ngrp) {
        float4 v = __ldcs(x4 + r * D4 + lane);    // L2 hit expected; evict after
        float4 o;
        o.x = fmaf(v.x, scale.x, shift.x);
        o.y = fmaf(v.y, scale.y, shift.y);
        o.z = fmaf(v.z, scale.z, shift.z);
        o.w = fmaf(v.w, scale.w, shift.w);
        __stcs(o4 + r * D4 + lane, o);            // streaming store
    }
}

// ---------------------------------------------------------------------------
// Scalar fallback (any shape) — proven in R3.
// ---------------------------------------------------------------------------
__global__ void pin_reduce_scalar(const float* __restrict__ x,
                                  const int*   __restrict__ seqlen, int D) {
    const int b = blockIdx.y;
    const int s = seqlen[b];
    const int e = seqlen[b + 1];
    const int L = e - s;
    const int nb = gridDim.x;
    const int chunk = (L + nb - 1) / nb;
    long long r0 = (long long)s + (long long)blockIdx.x * chunk;
    long long r1 = (long long)s + (long long)min((long long)L,
                                                 (long long)(blockIdx.x + 1) * (long long)chunk);
    for (int d = threadIdx.x; d < D; d += blockDim.x) {
        float sum = 0.f, sq = 0.f;
        for (long long r = r0; r < r1; r++) {
            float v = x[r * D + d];
            sum += v; sq += v * v;
        }
        atomicAdd(&g_sum[b * D + d], sum);
        atomicAdd(&g_sq [b * D + d], sq);
    }
}

__global__ void pin_finalize_kernel(const int*   __restrict__ seqlen,
                                    const float* __restrict__ w,
                                    const float* __restrict__ bias,
                                    int B, int D) {
    int i = blockIdx.x * blockDim.x + threadIdx.x;
    if (i >= B * D) return;
    int b = i / D;
    int d = i - b * D;
    float denom = fmaxf((float)(seqlen[b + 1] - seqlen[b]), 1.0f);
    float mean  = g_sum[i] / denom;
    float var   = fmaxf(g_sq[i] / denom - mean * mean, 0.0f);
    float sc = rsqrtf(var + PIN_EPS) * w[d];
    g_scale[i] = sc;
    g_shift[i] = bias[d] - mean * sc;
}

__global__ void pin_norm_scalar(const float* __restrict__ x,
                                const int*   __restrict__ seqlen,
                                float*       __restrict__ out, int D) {
    const int b = blockIdx.y;
    const int s = seqlen[b];
    const int e = seqlen[b + 1];
    const int L = e - s;
    const int nb = gridDim.x;
    const int chunk = (L + nb - 1) / nb;
    long long r0 = (long long)s + (long long)blockIdx.x * chunk;
    long long r1 = (long long)s + (long long)min((long long)L,
                                                 (long long)(blockIdx.x + 1) * (long long)chunk);
    for (long long r = r0; r < r1; r++) {
        for (int d = threadIdx.x; d < D; d += blockDim.x) {
            float v = x[r * D + d];
            out[r * D + d] = fmaf(v, g_scale[b * D + d], g_shift[b * D + d]);
        }
    }
}

// ---------------------------------------------------------------------------
// Host side: 2-stream pipeline, capture-safe (fork/join via events).
// ---------------------------------------------------------------------------
static bool         s_init = false;
static cudaStream_t s_side;
static cudaEvent_t  s_ev_zero;
static cudaEvent_t  s_evR[PIN_MAXB];   // reduce(b) done
static cudaEvent_t  s_evN[PIN_MAXB];   // norm(b) done

extern "C" void kernel_launch(void* const* d_in, const int* in_sizes, int n_in,
                              void* d_out, int out_size) {
    const float* x      = (const float*)d_in[0];
    const int*   seqlen = (const int*)  d_in[1];
    const float* weight = (const float*)d_in[2];
    const float* bias   = (const float*)d_in[3];
    float*       out    = (float*)d_out;

    const int D  = in_sizes[2];          // weight is [1, D]
    const int B  = in_sizes[1] - 1;      // seqlen is [B+1]
    const long long N = (D > 0) ? (long long)in_sizes[0] / D : 0;
    const int BD = B * D;

    const int D4 = D / 4;
    const bool vec_ok = (D > 0) && (D % 4 == 0) && (D4 >= 1) && (D4 <= 256) &&
                        (BD <= PIN_MAXBD) && (B >= 1) && (B <= PIN_MAXB);

    int nblk = 0;
    if (vec_ok) {
        int dev = 0, sms = 0, per_sm = 0;
        cudaGetDevice(&dev);
        cudaDeviceGetAttribute(&sms, cudaDevAttrMultiProcessorCount, dev);
        cudaOccupancyMaxActiveBlocksPerMultiprocessor(&per_sm, pin_reduce_seg,
                                                      256, 0);
        if (sms > 0 && per_sm > 0) nblk = sms * per_sm;   // single wave
        if (nblk > 4096) nblk = 4096;
    }

    if (nblk >= 1) {
        if (!s_init) {
            cudaStreamCreateWithFlags(&s_side, cudaStreamNonBlocking);
            cudaEventCreateWithFlags(&s_ev_zero, cudaEventDisableTiming);
            for (int i = 0; i < PIN_MAXB; i++) {
                cudaEventCreateWithFlags(&s_evR[i], cudaEventDisableTiming);
                cudaEventCreateWithFlags(&s_evN[i], cudaEventDisableTiming);
            }
            s_init = true;
        }

        // zero accumulators on the main stream, then fork the side stream
        {
            int threads = 256;
            int blocks = (BD + threads - 1) / threads;
            pin_zero_kernel<<<blocks, threads>>>(BD);
        }
        cudaEventRecord(s_ev_zero, 0);
        cudaStreamWaitEvent(s_side, s_ev_zero, 0);

        for (int b = 0; b < B; b++) {
            // backpressure: reduce(b) may run once norm(b-2) has drained,
            // keeping the L2 set to ~3 segments + 1 out tile.
            if (b >= 2) cudaStreamWaitEvent(s_side, s_evN[b - 2], 0);
            pin_reduce_seg<<<nblk, 256, 0, s_side>>>(x, seqlen, b, D4);
            cudaEventRecord(s_evR[b], s_side);

            cudaStreamWaitEvent(0, s_evR[b], 0);
            pin_norm_seg<<<nblk, 256>>>(x, seqlen, weight, bias, out, b, D4);
            cudaEventRecord(s_evN[b], 0);
        }
        // everything joins back into the main stream via s_evR[B-1]->norm(B-1)
        return;
    }

    // ---- Fallback: scalar 4-kernel pipeline ----
    {
        int threads = 256;
        int blocks = (BD + threads - 1) / threads;
        if (blocks < 1) blocks = 1;
        pin_zero_kernel<<<blocks, threads>>>(BD);
    }
    int Bx = (B > 0) ? B : 1;
    int chunks = (4096 + Bx - 1) / Bx;
    long long avg_rows = (N + Bx - 1) / Bx;
    if ((long long)chunks > avg_rows && avg_rows > 0) chunks = (int)avg_rows;
    if (chunks < 1) chunks = 1;
    dim3 grid(chunks, Bx);
    pin_reduce_scalar<<<grid, 256>>>(x, seqlen, D);
    {
        int threads = 256;
        int blocks = (BD + threads - 1) / threads;
        if (blocks < 1) blocks = 1;
        pin_finalize_kernel<<<blocks, threads>>>(seqlen, weight, bias, B, D);
    }
    pin_norm_scalar<<<grid, 256>>>(x, seqlen, out, D);
}

// round 7
// speedup vs baseline: 2.1661x; 2.1661x over previous
#include <cuda_runtime.h>
#include <cuda_bf16.h>

// PointInstanceNorm — tuned two-pass version (R3 structure).
// x: [N,D] fp32; seqlen: [B+1] cumulative; weight/bias: [D].
// out[i,d] = (x[i,d]-mean[b,d]) * rsqrt(var[b,d]+eps) * w[d] + bias[d].
//
// R4/R5 lesson: cross-pass L2 reuse loses more to sync/ramp than it saves.
// This round: bulk two-pass, plus
//   (1) norm traverses chunks in REVERSE so its first reads hit the L2 tail
//       left behind by reduce (free ~100MB DRAM savings),
//   (2) reduce uses 4 independent accumulator sets (higher MLP),
//   (3) no atomics: per-chunk partials + tiny finalize (no zero kernel).

#define PIN_EPS 1e-5f
#define PIN_MAXBD   (1 << 20)
#define PIN_PARTCAP (1 << 22)   // max chunks*B*D partial floats (16 MB/array)

__device__ float g_psum [PIN_PARTCAP];
__device__ float g_psq  [PIN_PARTCAP];
__device__ float g_scale[PIN_MAXBD];
__device__ float g_shift[PIN_MAXBD];
// scalar-fallback scratch
__device__ float g_sum[PIN_MAXBD];
__device__ float g_sq [PIN_MAXBD];

// ---------------------------------------------------------------------------
// Pass 1: reduce. grid=(chunks,B), block=256. Contiguous row chunk per block.
// Writes per-chunk partial sums (no atomics). Default cache policy so the
// tail of x stays L2-resident for the reversed norm pass.
// ---------------------------------------------------------------------------
__global__ void __launch_bounds__(256)
pin_reduce_kernel(const float* __restrict__ x,
                  const int*   __restrict__ seqlen,
                  int D4, int BD) {
    const int c  = blockIdx.x;
    const int b  = blockIdx.y;
    const long long s = seqlen[b];
    const long long e = seqlen[b + 1];
    const int L  = (int)(e - s);
    const int nb = gridDim.x;
    const int chunk = (L + nb - 1) / nb;
    const long long r0 = s + (long long)c * chunk;
    const long long r1 = s + (long long)min((long long)L,
                                            (long long)(c + 1) * (long long)chunk);
    const int lane = threadIdx.x % D4;
    const int grp  = threadIdx.x / D4;
    const int ngrp = blockDim.x / D4;
    const int D    = D4 * 4;

    float4 s0 = make_float4(0,0,0,0), s1 = s0, s2 = s0, s3 = s0;
    float4 q0 = s0, q1 = s0, q2 = s0, q3 = s0;

    if (grp < ngrp) {
        const float4* __restrict__ x4 = (const float4*)x;
        long long r = r0 + grp;
        const long long step = ngrp;
        // 4-way unrolled: independent loads + independent accumulator chains
        for (; r + 3 * step < r1; r += 4 * step) {
            float4 v0 = x4[(r           ) * D4 + lane];
            float4 v1 = x4[(r +     step) * D4 + lane];
            float4 v2 = x4[(r + 2 * step) * D4 + lane];
            float4 v3 = x4[(r + 3 * step) * D4 + lane];
            s0.x += v0.x; s0.y += v0.y; s0.z += v0.z; s0.w += v0.w;
            q0.x += v0.x*v0.x; q0.y += v0.y*v0.y; q0.z += v0.z*v0.z; q0.w += v0.w*v0.w;
            s1.x += v1.x; s1.y += v1.y; s1.z += v1.z; s1.w += v1.w;
            q1.x += v1.x*v1.x; q1.y += v1.y*v1.y; q1.z += v1.z*v1.z; q1.w += v1.w*v1.w;
            s2.x += v2.x; s2.y += v2.y; s2.z += v2.z; s2.w += v2.w;
            q2.x += v2.x*v2.x; q2.y += v2.y*v2.y; q2.z += v2.z*v2.z; q2.w += v2.w*v2.w;
            s3.x += v3.x; s3.y += v3.y; s3.z += v3.z; s3.w += v3.w;
            q3.x += v3.x*v3.x; q3.y += v3.y*v3.y; q3.z += v3.z*v3.z; q3.w += v3.w*v3.w;
        }
        for (; r < r1; r += step) {
            float4 v = x4[r * D4 + lane];
            s0.x += v.x; s0.y += v.y; s0.z += v.z; s0.w += v.w;
            q0.x += v.x*v.x; q0.y += v.y*v.y; q0.z += v.z*v.z; q0.w += v.w*v.w;
        }
    }
    // combine the 4 chains
    s0.x += s1.x + s2.x + s3.x;  s0.y += s1.y + s2.y + s3.y;
    s0.z += s1.z + s2.z + s3.z;  s0.w += s1.w + s2.w + s3.w;
    q0.x += q1.x + q2.x + q3.x;  q0.y += q1.y + q2.y + q3.y;
    q0.z += q1.z + q2.z + q3.z;  q0.w += q1.w + q2.w + q3.w;

    __shared__ float4 sh_s[256];
    __shared__ float4 sh_q[256];
    sh_s[threadIdx.x] = s0;
    sh_q[threadIdx.x] = q0;
    __syncthreads();

    if (grp == 0) {
        for (int g = 1; g < ngrp; g++) {
            float4 a = sh_s[g * D4 + lane];
            float4 cq = sh_q[g * D4 + lane];
            s0.x += a.x;  s0.y += a.y;  s0.z += a.z;  s0.w += a.w;
            q0.x += cq.x; q0.y += cq.y; q0.z += cq.z; q0.w += cq.w;
        }
        // distinct slot per (chunk, b, lane) — no atomics needed
        const long long o = (long long)c * BD + b * D + lane * 4;
        ((float4*)(g_psum + o))[0] = s0;
        ((float4*)(g_psq  + o))[0] = q0;
    }
}

// ---------------------------------------------------------------------------
// Finalize: sum partials over chunks, produce scale/shift. grid covers BD.
// ---------------------------------------------------------------------------
__global__ void pin_finalize_kernel(const int*   __restrict__ seqlen,
                                    const float* __restrict__ w,
                                    const float* __restrict__ bias,
                                    int B, int D, int chunks) {
    int i = blockIdx.x * blockDim.x + threadIdx.x;
    int BD = B * D;
    if (i >= BD) return;
    int b = i / D;
    int d = i - b * D;

    float sum = 0.f, sq = 0.f;
    for (int c = 0; c < chunks; c++) {
        long long o = (long long)c * BD + i;
        sum += g_psum[o];
        sq  += g_psq [o];
    }
    float denom = fmaxf((float)(seqlen[b + 1] - seqlen[b]), 1.0f);
    float mean  = sum / denom;
    float var   = fmaxf(sq / denom - mean * mean, 0.0f);
    float sc = rsqrtf(var + PIN_EPS) * w[d];
    g_scale[i] = sc;
    g_shift[i] = bias[d] - mean * sc;
}

// ---------------------------------------------------------------------------
// Pass 2: normalize. Same grid shape, but blocks are mapped to chunks in
// REVERSE so the first-processed rows are the ones reduce left in L2.
// x reads .cs (last use, evict-first); out writes .cs (streaming).
// ---------------------------------------------------------------------------
__global__ void __launch_bounds__(256)
pin_norm_kernel(const float* __restrict__ x,
                const int*   __restrict__ seqlen,
                float*       __restrict__ out,
                int D4) {
    const int c = gridDim.x - 1 - blockIdx.x;   // reversed chunk
    const int b = gridDim.y - 1 - blockIdx.y;   // reversed segment
    const long long s = seqlen[b];
    const long long e = seqlen[b + 1];
    const int L  = (int)(e - s);
    const int nb = gridDim.x;
    const int chunk = (L + nb - 1) / nb;
    const long long r0 = s + (long long)c * chunk;
    const long long r1 = s + (long long)min((long long)L,
                                            (long long)(c + 1) * (long long)chunk);
    const int lane = threadIdx.x % D4;
    const int grp  = threadIdx.x / D4;
    const int ngrp = blockDim.x / D4;
    if (grp >= ngrp) return;

    const float4 sc = __ldcg(((const float4*)g_scale) + b * D4 + lane);
    const float4 sh = __ldcg(((const float4*)g_shift) + b * D4 + lane);
    const float4* __restrict__ x4 = (const float4*)x;
    float4*       __restrict__ o4 = (float4*)out;

    for (long long r = r0 + grp; r < r1; r += ngrp) {
        float4 v = __ldcs(x4 + r * D4 + lane);
        float4 o;
        o.x = fmaf(v.x, sc.x, sh.x);
        o.y = fmaf(v.y, sc.y, sh.y);
        o.z = fmaf(v.z, sc.z, sh.z);
        o.w = fmaf(v.w, sc.w, sh.w);
        __stcs(o4 + r * D4 + lane, o);
    }
}

// ---------------------------------------------------------------------------
// Scalar fallback (any shape) — proven in R3.
// ---------------------------------------------------------------------------
__global__ void pin_zero_kernel(int n) {
    int i = blockIdx.x * blockDim.x + threadIdx.x;
    if (i < n) { g_sum[i] = 0.0f; g_sq[i] = 0.0f; }
}

__global__ void pin_reduce_scalar(const float* __restrict__ x,
                                  const int*   __restrict__ seqlen, int D) {
    const int b = blockIdx.y;
    const int s = seqlen[b];
    const int e = seqlen[b + 1];
    const int L = e - s;
    const int nb = gridDim.x;
    const int chunk = (L + nb - 1) / nb;
    long long r0 = (long long)s + (long long)blockIdx.x * chunk;
    long long r1 = (long long)s + (long long)min((long long)L,
                                                 (long long)(blockIdx.x + 1) * (long long)chunk);
    for (int d = threadIdx.x; d < D; d += blockDim.x) {
        float sum = 0.f, sq = 0.f;
        for (long long r = r0; r < r1; r++) {
            float v = x[r * D + d];
            sum += v; sq += v * v;
        }
        atomicAdd(&g_sum[b * D + d], sum);
        atomicAdd(&g_sq [b * D + d], sq);
    }
}

__global__ void pin_finalize_scalar(const int*   __restrict__ seqlen,
                                    const float* __restrict__ w,
                                    const float* __restrict__ bias,
                                    int B, int D) {
    int i = blockIdx.x * blockDim.x + threadIdx.x;
    if (i >= B * D) return;
    int b = i / D;
    int d = i - b * D;
    float denom = fmaxf((float)(seqlen[b + 1] - seqlen[b]), 1.0f);
    float mean  = g_sum[i] / denom;
    float var   = fmaxf(g_sq[i] / denom - mean * mean, 0.0f);
    float sc = rsqrtf(var + PIN_EPS) * w[d];
    g_scale[i] = sc;
    g_shift[i] = bias[d] - mean * sc;
}

__global__ void pin_norm_scalar(const float* __restrict__ x,
                                const int*   __restrict__ seqlen,
                                float*       __restrict__ out, int D) {
    const int b = blockIdx.y;
    const int s = seqlen[b];
    const int e = seqlen[b + 1];
    const int L = e - s;
    const int nb = gridDim.x;
    const int chunk = (L + nb - 1) / nb;
    long long r0 = (long long)s + (long long)blockIdx.x * chunk;
    long long r1 = (long long)s + (long long)min((long long)L,
                                                 (long long)(blockIdx.x + 1) * (long long)chunk);
    for (long long r = r0; r < r1; r++) {
        for (int d = threadIdx.x; d < D; d += blockDim.x) {
            float v = x[r * D + d];
            out[r * D + d] = fmaf(v, g_scale[b * D + d], g_shift[b * D + d]);
        }
    }
}

extern "C" void kernel_launch(void* const* d_in, const int* in_sizes, int n_in,
                              void* d_out, int out_size) {
    const float* x      = (const float*)d_in[0];
    const int*   seqlen = (const int*)  d_in[1];
    const float* weight = (const float*)d_in[2];
    const float* bias   = (const float*)d_in[3];
    float*       out    = (float*)d_out;

    const int D  = in_sizes[2];          // weight is [1, D]
    const int B  = in_sizes[1] - 1;      // seqlen is [B+1]
    const long long N = (D > 0) ? (long long)in_sizes[0] / D : 0;
    const int BD = B * D;

    const int D4 = D / 4;
    const bool vec_ok = (D > 0) && (D % 4 == 0) && (D4 >= 1) && (D4 <= 256) &&
                        (BD > 0) && (BD <= PIN_MAXBD);

    // Chunks per segment: ~4096 total blocks (same as the 264us R3 config),
    // bounded by the partial-array capacity and rows available.
    int chunks = 0;
    if (vec_ok) {
        int Bx = B;
        chunks = (4096 + Bx - 1) / Bx;
        long long avg_rows = (N + Bx - 1) / Bx;
        if ((long long)chunks > avg_rows && avg_rows > 0) chunks = (int)avg_rows;
        while ((long long)chunks * BD > PIN_PARTCAP && chunks > 1) chunks >>= 1;
        if (chunks < 1) chunks = 1;
    }

    if (vec_ok && chunks >= 1) {
        dim3 grid(chunks, B);
        pin_reduce_kernel<<<grid, 256>>>(x, seqlen, D4, BD);
        {
            int threads = 256;
            int blocks = (BD + threads - 1) / threads;
            pin_finalize_kernel<<<blocks, threads>>>(seqlen, weight, bias,
                                                     B, D, chunks);
        }
        pin_norm_kernel<<<grid, 256>>>(x, seqlen, out, D4);
        return;
    }

    // ---- Fallback: scalar 4-kernel pipeline (any shape) ----
    {
        int threads = 256;
        int blocks = (BD + threads - 1) / threads;
        if (blocks < 1) blocks = 1;
        pin_zero_kernel<<<blocks, threads>>>(BD);
    }
    int Bx = (B > 0) ? B : 1;
    int ch = (4096 + Bx - 1) / Bx;
    long long avg_rows = (N + Bx - 1) / Bx;
    if ((long long)ch > avg_rows && avg_rows > 0) ch = (int)avg_rows;
    if (ch < 1) ch = 1;
    dim3 grid(ch, Bx);
    pin_reduce_scalar<<<grid, 256>>>(x, seqlen, D);
    {
        int threads = 256;
        int blocks = (BD + threads - 1) / threads;
        if (blocks < 1) blocks = 1;
        pin_finalize_scalar<<<blocks, threads>>>(seqlen, weight, bias, B, D);
    }
    pin_norm_scalar<<<grid, 256>>>(x, seqlen, out, D);
}

// round 9
// speedup vs baseline: 2.4493x; 1.1307x over previous
#include <cuda_runtime.h>
#include <cuda_bf16.h>

// PointInstanceNorm — two-pass, R3-proven norm + single-wave reduce.
// x: [N,D] fp32; seqlen: [B+1] cumulative; weight/bias: [D].
// out[i,d] = (x[i,d]-mean[b,d]) * rsqrt(var[b,d]+eps) * w[d] + bias[d].
//
// R6 post-mortem: .cs policy + reversed mapping regressed norm by ~27us ->
// norm restored to the exact R3 form (plain loads/stores, forward order,
// 4096 blocks). Reduce rebuilt as a SINGLE co-resident wave (occupancy-API
// sized) with 2-way unroll: long per-CTA loops dilute multi-CTA spread to
// its floor, 2 outstanding warp-loads cover DRAM latency, regs stay low.

#define PIN_EPS 1e-5f
#define PIN_MAXBD   (1 << 20)
#define PIN_PARTCAP (1 << 22)

__device__ float g_psum [PIN_PARTCAP];
__device__ float g_psq  [PIN_PARTCAP];
__device__ float g_scale[PIN_MAXBD];
__device__ float g_shift[PIN_MAXBD];
// scalar-fallback scratch
__device__ float g_sum[PIN_MAXBD];
__device__ float g_sq [PIN_MAXBD];

// ---------------------------------------------------------------------------
// Pass 1: reduce. grid=(chunks,B) sized to ONE resident wave. block=256.
// 2-way unroll (2 independent loads + 2 accumulator chains), no atomics:
// per-(chunk,b) partials.
// ---------------------------------------------------------------------------
__global__ void __launch_bounds__(256)
pin_reduce_kernel(const float* __restrict__ x,
                  const int*   __restrict__ seqlen,
                  int D4, int BD) {
    const int c  = blockIdx.x;
    const int b  = blockIdx.y;
    const long long s = seqlen[b];
    const long long e = seqlen[b + 1];
    const int L  = (int)(e - s);
    const int nb = gridDim.x;
    const int chunk = (L + nb - 1) / nb;
    const long long r0 = s + (long long)c * chunk;
    const long long r1 = s + (long long)min((long long)L,
                                            (long long)(c + 1) * (long long)chunk);
    const int lane = threadIdx.x % D4;
    const int grp  = threadIdx.x / D4;
    const int ngrp = blockDim.x / D4;
    const int D    = D4 * 4;

    float4 s0 = make_float4(0.f, 0.f, 0.f, 0.f), s1 = s0;
    float4 q0 = s0, q1 = s0;

    if (grp < ngrp) {
        const float4* __restrict__ x4 = (const float4*)x;
        const long long step = ngrp;
        long long r = r0 + grp;
        for (; r + step < r1; r += 2 * step) {
            float4 v0 = x4[(r       ) * D4 + lane];
            float4 v1 = x4[(r + step) * D4 + lane];
            s0.x += v0.x; s0.y += v0.y; s0.z += v0.z; s0.w += v0.w;
            q0.x += v0.x * v0.x; q0.y += v0.y * v0.y;
            q0.z += v0.z * v0.z; q0.w += v0.w * v0.w;
            s1.x += v1.x; s1.y += v1.y; s1.z += v1.z; s1.w += v1.w;
            q1.x += v1.x * v1.x; q1.y += v1.y * v1.y;
            q1.z += v1.z * v1.z; q1.w += v1.w * v1.w;
        }
        if (r < r1) {
            float4 v = x4[r * D4 + lane];
            s0.x += v.x; s0.y += v.y; s0.z += v.z; s0.w += v.w;
            q0.x += v.x * v.x; q0.y += v.y * v.y;
            q0.z += v.z * v.z; q0.w += v.w * v.w;
        }
    }
    s0.x += s1.x; s0.y += s1.y; s0.z += s1.z; s0.w += s1.w;
    q0.x += q1.x; q0.y += q1.y; q0.z += q1.z; q0.w += q1.w;

    __shared__ float4 sh_s[256];
    __shared__ float4 sh_q[256];
    sh_s[threadIdx.x] = s0;
    sh_q[threadIdx.x] = q0;
    __syncthreads();

    if (grp == 0) {
        for (int g = 1; g < ngrp; g++) {
            float4 a  = sh_s[g * D4 + lane];
            float4 cq = sh_q[g * D4 + lane];
            s0.x += a.x;  s0.y += a.y;  s0.z += a.z;  s0.w += a.w;
            q0.x += cq.x; q0.y += cq.y; q0.z += cq.z; q0.w += cq.w;
        }
        const long long o = (long long)c * BD + b * D + lane * 4;
        ((float4*)(g_psum + o))[0] = s0;
        ((float4*)(g_psq  + o))[0] = q0;
    }
}

// ---------------------------------------------------------------------------
// Finalize: sum partials over chunks -> scale/shift. grid covers BD.
// ---------------------------------------------------------------------------
__global__ void pin_finalize_kernel(const int*   __restrict__ seqlen,
                                    const float* __restrict__ w,
                                    const float* __restrict__ bias,
                                    int B, int D, int chunks) {
    int i = blockIdx.x * blockDim.x + threadIdx.x;
    int BD = B * D;
    if (i >= BD) return;
    int b = i / D;
    int d = i - b * D;

    float sum = 0.f, sq = 0.f;
    for (int c = 0; c < chunks; c++) {
        long long o = (long long)c * BD + i;
        sum += g_psum[o];
        sq  += g_psq [o];
    }
    float denom = fmaxf((float)(seqlen[b + 1] - seqlen[b]), 1.0f);
    float mean  = sum / denom;
    float var   = fmaxf(sq / denom - mean * mean, 0.0f);
    float sc = rsqrtf(var + PIN_EPS) * w[d];
    g_scale[i] = sc;
    g_shift[i] = bias[d] - mean * sc;
}

// ---------------------------------------------------------------------------
// Pass 2: normalize — EXACT R3 form (153.5us @ 6.36TB/s measured):
// forward mapping, plain loads/stores, fma epilogue.
// ---------------------------------------------------------------------------
__global__ void __launch_bounds__(256)
pin_norm_kernel(const float* __restrict__ x,
                const int*   __restrict__ seqlen,
                float*       __restrict__ out,
                int D4) {
    const int b = blockIdx.y;
    const long long s = seqlen[b];
    const long long e = seqlen[b + 1];
    const int L  = (int)(e - s);
    const int nb = gridDim.x;
    const int chunk = (L + nb - 1) / nb;
    const long long r0 = s + (long long)blockIdx.x * chunk;
    const long long r1 = s + (long long)min((long long)L,
                                            (long long)(blockIdx.x + 1) * (long long)chunk);
    const int lane = threadIdx.x % D4;
    const int grp  = threadIdx.x / D4;
    const int ngrp = blockDim.x / D4;
    if (grp >= ngrp) return;

    const float4 sc = ((const float4*)g_scale)[b * D4 + lane];
    const float4 sh = ((const float4*)g_shift)[b * D4 + lane];
    const float4* __restrict__ x4 = (const float4*)x;
    float4* __restrict__ o4 = (float4*)out;

    for (long long r = r0 + grp; r < r1; r += ngrp) {
        float4 v = x4[r * D4 + lane];
        float4 o;
        o.x = fmaf(v.x, sc.x, sh.x);
        o.y = fmaf(v.y, sc.y, sh.y);
        o.z = fmaf(v.z, sc.z, sh.z);
        o.w = fmaf(v.w, sc.w, sh.w);
        o4[r * D4 + lane] = o;
    }
}

// ---------------------------------------------------------------------------
// Scalar fallback (any shape).
// ---------------------------------------------------------------------------
__global__ void pin_zero_kernel(int n) {
    int i = blockIdx.x * blockDim.x + threadIdx.x;
    if (i < n) { g_sum[i] = 0.0f; g_sq[i] = 0.0f; }
}

__global__ void pin_reduce_scalar(const float* __restrict__ x,
                                  const int*   __restrict__ seqlen, int D) {
    const int b = blockIdx.y;
    const int s = seqlen[b];
    const int e = seqlen[b + 1];
    const int L = e - s;
    const int nb = gridDim.x;
    const int chunk = (L + nb - 1) / nb;
    long long r0 = (long long)s + (long long)blockIdx.x * chunk;
    long long r1 = (long long)s + (long long)min((long long)L,
                                                 (long long)(blockIdx.x + 1) * (long long)chunk);
    for (int d = threadIdx.x; d < D; d += blockDim.x) {
        float sum = 0.f, sq = 0.f;
        for (long long r = r0; r < r1; r++) {
            float v = x[r * D + d];
            sum += v; sq += v * v;
        }
        atomicAdd(&g_sum[b * D + d], sum);
        atomicAdd(&g_sq [b * D + d], sq);
    }
}

__global__ void pin_finalize_scalar(const int*   __restrict__ seqlen,
                                    const float* __restrict__ w,
                                    const float* __restrict__ bias,
                                    int B, int D) {
    int i = blockIdx.x * blockDim.x + threadIdx.x;
    if (i >= B * D) return;
    int b = i / D;
    int d = i - b * D;
    float denom = fmaxf((float)(seqlen[b + 1] - seqlen[b]), 1.0f);
    float mean  = g_sum[i] / denom;
    float var   = fmaxf(g_sq[i] / denom - mean * mean, 0.0f);
    float sc = rsqrtf(var + PIN_EPS) * w[d];
    g_scale[i] = sc;
    g_shift[i] = bias[d] - mean * sc;
}

__global__ void pin_norm_scalar(const float* __restrict__ x,
                                const int*   __restrict__ seqlen,
                                float*       __restrict__ out, int D) {
    const int b = blockIdx.y;
    const int s = seqlen[b];
    const int e = seqlen[b + 1];
    const int L = e - s;
    const int nb = gridDim.x;
    const int chunk = (L + nb - 1) / nb;
    long long r0 = (long long)s + (long long)blockIdx.x * chunk;
    long long r1 = (long long)s + (long long)min((long long)L,
                                                 (long long)(blockIdx.x + 1) * (long long)chunk);
    for (long long r = r0; r < r1; r++) {
        for (int d = threadIdx.x; d < D; d += blockDim.x) {
            float v = x[r * D + d];
            out[r * D + d] = fmaf(v, g_scale[b * D + d], g_shift[b * D + d]);
        }
    }
}

extern "C" void kernel_launch(void* const* d_in, const int* in_sizes, int n_in,
                              void* d_out, int out_size) {
    const float* x      = (const float*)d_in[0];
    const int*   seqlen = (const int*)  d_in[1];
    const float* weight = (const float*)d_in[2];
    const float* bias   = (const float*)d_in[3];
    float*       out    = (float*)d_out;

    const int D  = in_sizes[2];          // weight is [1, D]
    const int B  = in_sizes[1] - 1;      // seqlen is [B+1]
    const long long N = (D > 0) ? (long long)in_sizes[0] / D : 0;
    const int BD = B * D;

    const int D4 = D / 4;
    const bool vec_ok = (D > 0) && (D % 4 == 0) && (D4 >= 1) && (D4 <= 256) &&
                        (BD > 0) && (BD <= PIN_MAXBD);

    if (vec_ok) {
        // ---- reduce: one resident wave ----
        int dev = 0, sms = 0, per_sm = 0;
        cudaGetDevice(&dev);
        cudaDeviceGetAttribute(&sms, cudaDevAttrMultiProcessorCount, dev);
        cudaOccupancyMaxActiveBlocksPerMultiprocessor(&per_sm, pin_reduce_kernel,
                                                      256, 0);
        if (sms <= 0) sms = 148;
        if (per_sm <= 0) per_sm = 4;
        int rchunks = (sms * per_sm) / B;            // one wave total
        if (rchunks < 1) rchunks = 1;
        long long avg_rows = (N + B - 1) / B;
        if ((long long)rchunks > avg_rows && avg_rows > 0)
            rchunks = (int)avg_rows;
        while ((long long)rchunks * BD > PIN_PARTCAP && rchunks > 1)
            rchunks >>= 1;

        // ---- norm: R3 config (~4096 blocks) ----
        int nchunks = (4096 + B - 1) / B;
        if ((long long)nchunks > avg_rows && avg_rows > 0)
            nchunks = (int)avg_rows;
        if (nchunks < 1) nchunks = 1;

        dim3 rgrid(rchunks, B);
        dim3 ngrid(nchunks, B);

        pin_reduce_kernel<<<rgrid, 256>>>(x, seqlen, D4, BD);
        {
            int threads = 256;
            int blocks = (BD + threads - 1) / threads;
            pin_finalize_kernel<<<blocks, threads>>>(seqlen, weight, bias,
                                                     B, D, rchunks);
        }
        pin_norm_kernel<<<ngrid, 256>>>(x, seqlen, out, D4);
        return;
    }

    // ---- Fallback: scalar 4-kernel pipeline (any shape) ----
    {
        int threads = 256;
        int blocks = (BD + threads - 1) / threads;
        if (blocks < 1) blocks = 1;
        pin_zero_kernel<<<blocks, threads>>>(BD);
    }
    int Bx = (B > 0) ? B : 1;
    int ch = (4096 + Bx - 1) / Bx;
    long long avg_rows = (N + Bx - 1) / Bx;
    if ((long long)ch > avg_rows && avg_rows > 0) ch = (int)avg_rows;
    if (ch < 1) ch = 1;
    dim3 grid(ch, Bx);
    pin_reduce_scalar<<<grid, 256>>>(x, seqlen, D);
    {
        int threads = 256;
        int blocks = (BD + threads - 1) / threads;
        if (blocks < 1) blocks = 1;
        pin_finalize_scalar<<<blocks, threads>>>(seqlen, weight, bias, B, D);
    }
    pin_norm_scalar<<<grid, 256>>>(x, seqlen, out, D);
}